// round 11
// baseline (speedup 1.0000x reference)
#include <cuda_runtime.h>
#include <cstdint>

#define ELN   512
#define EL2   (512*512)
#define NIMG  128
#define KROWS 264                         // 257 used, padded to 264 (mult of 8)
#define IMGSTRIDE ((size_t)KROWS * ELN)   // complex elements per image
#define WIN   256
#define WIN0  128
#define PI_F  3.14159265358979323846f

// ---------------- device scratch (allocation-free) -------------------------
__device__ float2   g_bufA[(size_t)NIMG * KROWS * ELN];   // ~138 MB
__device__ float2   g_bufB[(size_t)NIMG * KROWS * ELN];   // ~138 MB (y=0..256 used)
__device__ float    g_win [(size_t)NIMG * WIN * WIN];     // 33.5 MB center window
__device__ unsigned g_mn[NIMG], g_mx[NIMG];
__device__ double   g_diff;

// ---------------- complex helpers -----------------------------------------
__device__ __forceinline__ float2 cmulf(float2 a, float2 b) {
    return make_float2(a.x * b.x - a.y * b.y, a.x * b.y + a.y * b.x);
}
__device__ __forceinline__ float2 caddf(float2 a, float2 b) {
    return make_float2(a.x + b.x, a.y + b.y);
}
__device__ __forceinline__ float2 csubf(float2 a, float2 b) {
    return make_float2(a.x - b.x, a.y - b.y);
}
__device__ __forceinline__ float2 shflx(float2 v, int m) {
    v.x = __shfl_xor_sync(0xffffffffu, v.x, m);
    v.y = __shfl_xor_sync(0xffffffffu, v.y, m);
    return v;
}
__device__ __forceinline__ int rev8(int k) { return __brev((unsigned)k) >> 24; }
__device__ __forceinline__ int sig(int k)  { return k ^ (k >> 4); }  // bank swizzle

// ============ 512-pt FFT (element e = lane + 32*j, j<16) ====================
__device__ __forceinline__ void fft512_dif_reg(float2 x[16], const float2* tw, int l) {
#pragma unroll
    for (int j = 0; j < 8; j++) {
        float2 w = tw[l + 32 * j];
        float2 a = x[j], b = x[j + 8];
        x[j]     = caddf(a, b);
        x[j + 8] = cmulf(csubf(a, b), w);
    }
#pragma unroll
    for (int g = 0; g < 2; g++)
#pragma unroll
        for (int j0 = 0; j0 < 4; j0++) {
            int j = g * 8 + j0;
            float2 w = tw[2 * (l + 32 * j0)];
            float2 a = x[j], b = x[j + 4];
            x[j]     = caddf(a, b);
            x[j + 4] = cmulf(csubf(a, b), w);
        }
#pragma unroll
    for (int g = 0; g < 4; g++)
#pragma unroll
        for (int j0 = 0; j0 < 2; j0++) {
            int j = g * 4 + j0;
            float2 w = tw[4 * (l + 32 * j0)];
            float2 a = x[j], b = x[j + 2];
            x[j]     = caddf(a, b);
            x[j + 2] = cmulf(csubf(a, b), w);
        }
    {
        float2 w = tw[8 * l];
#pragma unroll
        for (int j = 0; j < 16; j += 2) {
            float2 a = x[j], b = x[j + 1];
            x[j]     = caddf(a, b);
            x[j + 1] = cmulf(csubf(a, b), w);
        }
    }
#pragma unroll
    for (int mm = 16; mm >= 1; mm >>= 1) {
        int t = l & (mm - 1);
        float2 w = tw[t * (256 / mm)];
        bool up = (l & mm) == 0;
#pragma unroll
        for (int j = 0; j < 16; j++) {
            float2 o  = shflx(x[j], mm);
            float2 ru = caddf(x[j], o);
            float2 rd = cmulf(csubf(o, x[j]), w);
            x[j] = up ? ru : rd;
        }
    }
}

__device__ __forceinline__ void fft512_dit_reg(float2 x[16], const float2* tw, int l) {
#pragma unroll
    for (int mm = 1; mm <= 16; mm <<= 1) {
        int t = l & (mm - 1);
        float2 w = tw[t * (256 / mm)];
        w.y = -w.y;
        bool up = (l & mm) == 0;
#pragma unroll
        for (int j = 0; j < 16; j++) {
            float2 o  = shflx(x[j], mm);
            float2 ru = caddf(x[j], cmulf(o, w));
            float2 rd = csubf(o, cmulf(x[j], w));
            x[j] = up ? ru : rd;
        }
    }
    {
        float2 w = tw[8 * l];
        w.y = -w.y;
#pragma unroll
        for (int j = 0; j < 16; j += 2) {
            float2 u = x[j], v = cmulf(x[j + 1], w);
            x[j]     = caddf(u, v);
            x[j + 1] = csubf(u, v);
        }
    }
#pragma unroll
    for (int g = 0; g < 4; g++)
#pragma unroll
        for (int j0 = 0; j0 < 2; j0++) {
            int j = g * 4 + j0;
            float2 w = tw[4 * (l + 32 * j0)];
            w.y = -w.y;
            float2 u = x[j], v = cmulf(x[j + 2], w);
            x[j]     = caddf(u, v);
            x[j + 2] = csubf(u, v);
        }
#pragma unroll
    for (int g = 0; g < 2; g++)
#pragma unroll
        for (int j0 = 0; j0 < 4; j0++) {
            int j = g * 8 + j0;
            float2 w = tw[2 * (l + 32 * j0)];
            w.y = -w.y;
            float2 u = x[j], v = cmulf(x[j + 4], w);
            x[j]     = caddf(u, v);
            x[j + 4] = csubf(u, v);
        }
#pragma unroll
    for (int j = 0; j < 8; j++) {
        float2 w = tw[l + 32 * j];
        w.y = -w.y;
        float2 u = x[j], v = cmulf(x[j + 8], w);
        x[j]     = caddf(u, v);
        x[j + 8] = csubf(u, v);
    }
}

// ============ 256-pt FFT (element e = lane + 32*j, j<8) =====================
__device__ __forceinline__ void fft256_dif_reg(float2 x[8], const float2* tw, int l) {
#pragma unroll
    for (int j = 0; j < 4; j++) {                       // span 128
        float2 w = tw[2 * (l + 32 * j)];
        float2 a = x[j], b = x[j + 4];
        x[j]     = caddf(a, b);
        x[j + 4] = cmulf(csubf(a, b), w);
    }
#pragma unroll
    for (int g = 0; g < 2; g++)                         // span 64
#pragma unroll
        for (int j0 = 0; j0 < 2; j0++) {
            int j = g * 4 + j0;
            float2 w = tw[4 * (l + 32 * j0)];
            float2 a = x[j], b = x[j + 2];
            x[j]     = caddf(a, b);
            x[j + 2] = cmulf(csubf(a, b), w);
        }
    {
        float2 w = tw[8 * l];                           // span 32
#pragma unroll
        for (int j = 0; j < 8; j += 2) {
            float2 a = x[j], b = x[j + 1];
            x[j]     = caddf(a, b);
            x[j + 1] = cmulf(csubf(a, b), w);
        }
    }
#pragma unroll
    for (int mm = 16; mm >= 1; mm >>= 1) {              // spans 16..1
        int t = l & (mm - 1);
        float2 w = tw[t * (256 / mm)];
        bool up = (l & mm) == 0;
#pragma unroll
        for (int j = 0; j < 8; j++) {
            float2 o  = shflx(x[j], mm);
            float2 ru = caddf(x[j], o);
            float2 rd = cmulf(csubf(o, x[j]), w);
            x[j] = up ? ru : rd;
        }
    }
}

__device__ __forceinline__ void fft256_dit_reg(float2 x[8], const float2* tw, int l) {
#pragma unroll
    for (int mm = 1; mm <= 16; mm <<= 1) {
        int t = l & (mm - 1);
        float2 w = tw[t * (256 / mm)];
        w.y = -w.y;
        bool up = (l & mm) == 0;
#pragma unroll
        for (int j = 0; j < 8; j++) {
            float2 o  = shflx(x[j], mm);
            float2 ru = caddf(x[j], cmulf(o, w));
            float2 rd = csubf(o, cmulf(x[j], w));
            x[j] = up ? ru : rd;
        }
    }
    {
        float2 w = tw[8 * l];
        w.y = -w.y;
#pragma unroll
        for (int j = 0; j < 8; j += 2) {
            float2 u = x[j], v = cmulf(x[j + 1], w);
            x[j]     = caddf(u, v);
            x[j + 1] = csubf(u, v);
        }
    }
#pragma unroll
    for (int g = 0; g < 2; g++)
#pragma unroll
        for (int j0 = 0; j0 < 2; j0++) {
            int j = g * 4 + j0;
            float2 w = tw[4 * (l + 32 * j0)];
            w.y = -w.y;
            float2 u = x[j], v = cmulf(x[j + 2], w);
            x[j]     = caddf(u, v);
            x[j + 2] = csubf(u, v);
        }
#pragma unroll
    for (int j = 0; j < 4; j++) {
        float2 w = tw[2 * (l + 32 * j)];
        w.y = -w.y;
        float2 u = x[j], v = cmulf(x[j + 4], w);
        x[j]     = caddf(u, v);
        x[j + 4] = csubf(u, v);
    }
}

__device__ __forceinline__ void init_twiddles(float2* tw) {
    float s, c;
    sincosf(-PI_F * (float)threadIdx.x * (1.0f / 256.0f), &s, &c);
    tw[threadIdx.x] = make_float2(c, s);   // tw[i] = W_512^i
}

// ---------------- K0 --------------------------------------------------------
__global__ void k_init() {
    int t = threadIdx.x;
    if (t < NIMG) { g_mn[t] = 0x7f800000u; g_mx[t] = 0u; }
    if (t == 0)   g_diff = 0.0;
}

// -------- K1: mf0 + R2C row FFT (256-pt packed) -> bufA[k][r], k=0..256 -----
// launch_bounds(256, 2): 128-reg budget -> no local-memory spill of FFT state.
__global__ void __launch_bounds__(256, 2) k_stage1(const float* __restrict__ inA,
                                                   const float* __restrict__ inB) {
    __shared__ float2 tw[256];
    __shared__ float2 zs[8][289];
    init_twiddles(tw);
    int l  = threadIdx.x & 31, wp = threadIdx.x >> 5;
    int img = blockIdx.y;
    int r0  = blockIdx.x << 3;
    int row = r0 + wp;
    const float* src = (img < 64) ? (inA + (size_t)img * EL2)
                                  : (inB + (size_t)(img - 64) * EL2);
    const float2* rp = (const float2*)(src + (size_t)row * ELN);
    float2 x[8];
#pragma unroll
    for (int j = 0; j < 8; j++) {            // z[m] = mf0[2m] + i mf0[2m+1]
        float2 v = rp[l + 32 * j];
        x[j] = make_float2(__expf(-8.0f * v.x * v.x), __expf(-8.0f * v.y * v.y));
    }
    __syncthreads();                          // twiddles ready
    fft256_dif_reg(x, tw, l);                 // pos p holds Z(rev8(p))
#pragma unroll
    for (int j = 0; j < 8; j++) { int p = l + 32 * j; zs[wp][sig(p)] = x[j]; }
    __syncwarp();
    // Hermitian unpack: H(k) = E + (-i W^k) O, E=(Z(k)+conj(Z(256-k)))/2
    float2 H[8];
#pragma unroll
    for (int j = 0; j < 8; j++) {
        int k  = l + 32 * j;                  // 0..255
        int k2 = (256 - k) & 255;
        float2 A  = zs[wp][sig(rev8(k))];     // Z(k)
        float2 Bc = zs[wp][sig(rev8(k2))];    // Z(256-k)
        float2 B  = make_float2(Bc.x, -Bc.y);
        float2 E  = make_float2(0.5f * (A.x + B.x), 0.5f * (A.y + B.y));
        float2 O  = make_float2(0.5f * (A.x - B.x), 0.5f * (A.y - B.y));
        float2 w  = tw[k];
        float2 f  = make_float2(w.y, -w.x);   // -i * W^k
        H[j] = caddf(E, cmulf(f, O));
    }
    float2 Z0 = zs[wp][0];                    // sig(0)=0; Z(0)
    __syncwarp();
#pragma unroll
    for (int j = 0; j < 8; j++) zs[wp][l + 32 * j] = H[j];
    if (l == 0) zs[wp][256] = make_float2(Z0.x - Z0.y, 0.0f);  // H(256)
    __syncthreads();
    float2* dst = g_bufA + (size_t)img * IMGSTRIDE;
    for (int i = threadIdx.x; i < 257 * 8; i += 256) {
        int k = i >> 3, rl = i & 7;
        dst[(size_t)k * ELN + r0 + rl] = zs[rl][k];
    }
}

// -------- K2: column FFT + power + column IFFT (per k1 = 0..256) ------------
// Post-power the column sequence is REAL -> inverse output is conjugate-even
// in y: c(y) = conj(c(512-y)). Store only y = 0..256.
__global__ void __launch_bounds__(256, 2) k_stage2() {
    __shared__ float2 tw[256];
    __shared__ float2 sh[8][513];
    init_twiddles(tw);
    int l  = threadIdx.x & 31, wp = threadIdx.x >> 5;
    int img = blockIdx.y;
    int kb  = blockIdx.x << 3;                // 0..256 (33 blocks; pad rows stay 0)
    const float2* src = g_bufA + (size_t)img * IMGSTRIDE + (size_t)(kb + wp) * ELN;
    float2 x[16];
#pragma unroll
    for (int j = 0; j < 16; j++) x[j] = src[l + 32 * j];
    __syncthreads();
    fft512_dif_reg(x, tw, l);
#pragma unroll
    for (int j = 0; j < 16; j++) {            // power / (el*el), elementwise
        float p = (x[j].x * x[j].x + x[j].y * x[j].y) * (1.0f / 262144.0f);
        x[j] = make_float2(p, 0.0f);
    }
    fft512_dit_reg(x, tw, l);
    const float sc = 1.0f / 512.0f;           // column half of ifft2 norm
#pragma unroll
    for (int j = 0; j < 16; j++)
        sh[wp][l + 32 * j] = make_float2(x[j].x * sc, x[j].y * sc);
    __syncthreads();
    float2* dst = g_bufB + (size_t)img * IMGSTRIDE;
    for (int i = threadIdx.x; i < 257 * 8; i += 256) {   // only y = 0..256
        int y = i >> 3, kl = i & 7;
        dst[(size_t)y * KROWS + kb + kl] = sh[kl][y];
    }
}

// -------- K3: C2R row inverse + fftshift + min/max + window write -----------
__global__ void __launch_bounds__(256, 2) k_stage3() {
    __shared__ float2 tw[256];
    __shared__ float2 hs[8][289];
    __shared__ float  smn[8], smx[8];
    init_twiddles(tw);
    int l  = threadIdx.x & 31, wp = threadIdx.x >> 5;
    int img = blockIdx.y;
    int y   = (blockIdx.x << 3) + wp;
    // conjugate-even reconstruction for y > 256
    int   ys  = (y <= 256) ? y : (512 - y);
    float cs  = (y <= 256) ? 1.0f : -1.0f;
    const float2* srcB = g_bufB + (size_t)img * IMGSTRIDE + (size_t)ys * KROWS;
#pragma unroll
    for (int j = 0; j < 8; j++) {
        int idx = l + 32 * j;
        float2 v = srcB[idx];
        hs[wp][sig(idx)] = make_float2(v.x, cs * v.y);
    }
    if (l == 0) {
        float2 v = srcB[256];
        hs[wp][sig(256)] = make_float2(v.x, cs * v.y);
    }
    __syncthreads();                          // hs + twiddles ready
    // Build Z(k) = E + iO at bit-rev positions for the 256-pt DIT
    float2 x[8];
#pragma unroll
    for (int j = 0; j < 8; j++) {
        int p  = l + 32 * j;
        int k  = rev8(p);                     // 0..255
        int km = 256 - k;                     // 1..256
        float2 Hk = hs[wp][sig(k)];
        float2 Hm = hs[wp][sig(km)];          // conj applied below
        float2 E  = make_float2(0.5f * (Hk.x + Hm.x), 0.5f * (Hk.y - Hm.y));
        float2 Od = make_float2(0.5f * (Hk.x - Hm.x), 0.5f * (Hk.y + Hm.y));
        float2 w  = tw[k];
        float2 wc = make_float2(w.x, -w.y);   // W^{-k}
        float2 O  = cmulf(Od, wc);
        x[j] = make_float2(E.x - O.y, E.y + O.x);   // E + i*O
    }
    fft256_dit_reg(x, tw, l);                 // z(m) natural; x[2m]=z.x, x[2m+1]=z.y
    int yy = y ^ 256;                         // fftshift rows
    bool rowin = (yy >= WIN0) && (yy < WIN0 + WIN);
    float* wdst = g_win + (size_t)img * (WIN * WIN) + (size_t)(yy - WIN0) * WIN;
    float mn = 3.0e38f, mx = -3.0e38f;
#pragma unroll
    for (int j = 0; j < 8; j++) {
        float v0 = x[j].x * (1.0f / 256.0f);  // row half of ifft2 norm (C2R form)
        float v1 = x[j].y * (1.0f / 256.0f);
        mn = fminf(mn, fminf(v0, v1));
        mx = fmaxf(mx, fmaxf(v0, v1));
        int m  = l + 32 * j;
        int ms = m ^ 128;                     // shifted col pair (2ms, 2ms+1)
        if (rowin && ms >= 64 && ms < 192)    // cols in [128, 384)
            ((float2*)wdst)[ms - 64] = make_float2(v0, v1);
    }
#pragma unroll
    for (int o = 16; o; o >>= 1) {
        mn = fminf(mn, __shfl_xor_sync(0xffffffffu, mn, o));
        mx = fmaxf(mx, __shfl_xor_sync(0xffffffffu, mx, o));
    }
    if (l == 0) { smn[wp] = mn; smx[wp] = mx; }
    __syncthreads();
    if (threadIdx.x == 0) {
        float m1 = smn[0], m2 = smx[0];
#pragma unroll
        for (int i = 1; i < 8; i++) { m1 = fminf(m1, smn[i]); m2 = fmaxf(m2, smx[i]); }
        atomicMin(&g_mn[img], __float_as_uint(m1));   // ac > 0 -> uint order ok
        atomicMax(&g_mx[img], __float_as_uint(m2));
    }
}

// -------- K4: raw copy + normalize*mask window + zeros + MSE ----------------
__global__ void __launch_bounds__(256) k_final(const float* __restrict__ inA,
                                               const float* __restrict__ inB,
                                               float* __restrict__ out) {
    __shared__ float ssum[8];
    int b = blockIdx.y;            // image 0..63
    int r = blockIdx.x;            // row 0..511
    float mnI = __uint_as_float(g_mn[b]);
    float mxI = __uint_as_float(g_mx[b]);
    float mnT = __uint_as_float(g_mn[b + 64]);
    float mxT = __uint_as_float(g_mx[b + 64]);
    float sI = 1.0f / (mxI - mnI + 1e-12f);
    float sT = 1.0f / (mxT - mnT + 1e-12f);
    const float* rawI = inA + (size_t)b * EL2 + (size_t)r * ELN;
    const float* rawT = inB + (size_t)b * EL2 + (size_t)r * ELN;
    const float* winI = g_win + (size_t)b * (WIN * WIN) + (size_t)(r - WIN0) * WIN;
    const float* winT = g_win + (size_t)(b + 64) * (WIN * WIN) + (size_t)(r - WIN0) * WIN;
    float* oI = out + 1 + (size_t)b * (ELN * 1024) + (size_t)r * 1024;
    float* oT = oI + (size_t)64 * ELN * 1024;
    bool rowin = (r >= WIN0) && (r < WIN0 + WIN);
    float dy = (float)(r - 256);
    float dy2 = dy * dy;
    float ls = 0.0f;
#pragma unroll
    for (int it = 0; it < 2; it++) {
        int c = threadIdx.x + it * 256;
        oI[c] = rawI[c];
        oT[c] = rawT[c];
        float ia = 0.0f, ta = 0.0f;
        if (rowin && c >= WIN0 && c < WIN0 + WIN) {
            float vI = winI[c - WIN0];
            float vT = winT[c - WIN0];
            float dx = (float)(c - 256);
            float mask = __expf(-fmaf(dx, dx, dy2) * (1.0f / 800.0f));
            ia = (vI - mnI) * sI * mask;
            ta = (vT - mnT) * sT * mask;
            float d = ia - ta;
            ls = fmaf(d, d, ls);
        }
        oI[512 + c] = ia;
        oT[512 + c] = ta;
    }
    int l = threadIdx.x & 31, wp = threadIdx.x >> 5;
#pragma unroll
    for (int o = 16; o; o >>= 1) ls += __shfl_xor_sync(0xffffffffu, ls, o);
    if (l == 0) ssum[wp] = ls;
    __syncthreads();
    if (threadIdx.x == 0) {
        float t = ssum[0];
#pragma unroll
        for (int i = 1; i < 8; i++) t += ssum[i];
        atomicAdd(&g_diff, (double)t);
    }
}

__global__ void k_write(float* __restrict__ out) {
    out[0] = (float)(g_diff * (1.0 / 16777216.0));   // mean over B*el*el
}

// ---------------- launch ----------------------------------------------------
extern "C" void kernel_launch(void* const* d_in, const int* in_sizes, int n_in,
                              void* d_out, int out_size) {
    const float* inA = (const float*)d_in[0];
    const float* inB = (const float*)d_in[1];
    float* out = (float*)d_out;
    (void)in_sizes; (void)n_in; (void)out_size;

    k_init  <<<1, 128>>>();
    k_stage1<<<dim3(64, 128), 256>>>(inA, inB);
    k_stage2<<<dim3(33, 128), 256>>>();
    k_stage3<<<dim3(64, 128), 256>>>();
    k_final <<<dim3(512, 64), 256>>>(inA, inB, out);
    k_write <<<1, 1>>>(out);
}

// round 12
// speedup vs baseline: 1.2430x; 1.2430x over previous
#include <cuda_runtime.h>
#include <cstdint>

#define ELN   512
#define EL2   (512*512)
#define NIMG  128
#define KROWS 264                         // 257 used, padded to 264 (mult of 8)
#define IMGSTRIDE ((size_t)KROWS * ELN)   // complex elements per image
#define WIN   256
#define WIN0  128
#define PI_F  3.14159265358979323846f

// ---------------- device scratch (allocation-free) -------------------------
__device__ float2   g_bufA[(size_t)NIMG * KROWS * ELN];   // ~138 MB
__device__ float2   g_bufB[(size_t)NIMG * KROWS * ELN];   // ~138 MB (y=0..256 used)
__device__ float    g_win [(size_t)NIMG * WIN * WIN];     // 33.5 MB center window
__device__ unsigned g_mn[NIMG], g_mx[NIMG];
__device__ double   g_diff;

// ---------------- complex helpers -----------------------------------------
__device__ __forceinline__ float2 cmulf(float2 a, float2 b) {
    return make_float2(a.x * b.x - a.y * b.y, a.x * b.y + a.y * b.x);
}
__device__ __forceinline__ float2 caddf(float2 a, float2 b) {
    return make_float2(a.x + b.x, a.y + b.y);
}
__device__ __forceinline__ float2 csubf(float2 a, float2 b) {
    return make_float2(a.x - b.x, a.y - b.y);
}
__device__ __forceinline__ float2 csq(float2 a) {
    return make_float2(a.x * a.x - a.y * a.y, 2.0f * a.x * a.y);
}
__device__ __forceinline__ float2 cneg(float2 a)  { return make_float2(-a.x, -a.y); }
__device__ __forceinline__ float2 conjf(float2 a) { return make_float2(a.x, -a.y); }
__device__ __forceinline__ float2 cmul_mi(float2 a) { return make_float2(a.y, -a.x); } // a * (-i)
__device__ __forceinline__ float2 shflx(float2 v, int m) {
    v.x = __shfl_xor_sync(0xffffffffu, v.x, m);
    v.y = __shfl_xor_sync(0xffffffffu, v.y, m);
    return v;
}
__device__ __forceinline__ int rev8(int k) { return __brev((unsigned)k) >> 24; }
__device__ __forceinline__ int sig(int k)  { return k ^ (k >> 4); }  // bank swizzle

// Compile-time twiddle constants
__device__ __forceinline__ float2 C16f(int j) {   // W_16^j = exp(-i pi j/8)
    const float2 C[8] = {
        { 1.0f, 0.0f}, { 0.92387953f,-0.38268343f}, { 0.70710678f,-0.70710678f},
        { 0.38268343f,-0.92387953f}, { 0.0f,-1.0f}, {-0.38268343f,-0.92387953f},
        {-0.70710678f,-0.70710678f}, {-0.92387953f,-0.38268343f}};
    return C[j];
}
__device__ __forceinline__ float2 C8f(int j) {    // W_8^j = exp(-i pi j/4)
    const float2 C[4] = {
        {1.0f, 0.0f}, {0.70710678f,-0.70710678f}, {0.0f,-1.0f},
        {-0.70710678f,-0.70710678f}};
    return C[j];
}
__device__ __forceinline__ float2 CRf(int j) {    // W_512^{rev3(j)}
    const float2 C[8] = {
        {1.0f, 0.0f},               {0.99879546f,-0.04906767f},
        {0.99969882f,-0.02454123f}, {0.99729046f,-0.07356456f},
        {0.99992470f,-0.01227154f}, {0.99811811f,-0.06132074f},
        {0.99932238f,-0.03680722f}, {0.99631261f,-0.08579731f}};
    return C[j];
}

// ---------------- register twiddles (no shared table) ----------------------
struct Tw512 { float2 b512, b256, b128, b64, v16, v8, v4, v2; };

__device__ __forceinline__ Tw512 make_tw(int l) {
    Tw512 t; float s, c;
    sincosf(-PI_F * (float)l * (1.0f / 256.0f), &s, &c);
    t.b512 = make_float2(c, s);          // W_512^l
    t.b256 = csq(t.b512);                // W_256^l
    t.b128 = csq(t.b256);                // W_128^l
    t.b64  = csq(t.b128);                // W_64^l
    float2 v = csq(t.b64); if (l & 16) v = cneg(v); t.v16 = v;   // W_32^{l&15}
    v = csq(v);            if (l & 8)  v = cneg(v); t.v8  = v;   // W_16^{l&7}
    v = csq(v);            if (l & 4)  v = cneg(v); t.v4  = v;   // W_8^{l&3}
    v = csq(v);            if (l & 2)  v = cneg(v); t.v2  = v;   // W_4^{l&1}
    return t;
}

// ---------------- shuffle-stage helpers ------------------------------------
template <int N>
__device__ __forceinline__ void dif_shfl(float2* x, int mm, float2 w, int l) {
    bool up = (l & mm) == 0;
#pragma unroll
    for (int j = 0; j < N; j++) {
        float2 o  = shflx(x[j], mm);
        float2 ru = caddf(x[j], o);
        float2 rd = cmulf(csubf(o, x[j]), w);
        x[j] = up ? ru : rd;
    }
}
template <int N>
__device__ __forceinline__ void dif_shfl1(float2* x, int l) {   // mm=1, w=1
    bool up = (l & 1) == 0;
#pragma unroll
    for (int j = 0; j < N; j++) {
        float2 o  = shflx(x[j], 1);
        float2 ru = caddf(x[j], o);
        float2 rd = csubf(o, x[j]);
        x[j] = up ? ru : rd;
    }
}
template <int N>
__device__ __forceinline__ void dit_shfl(float2* x, int mm, float2 wc, int l) {
    bool up = (l & mm) == 0;
#pragma unroll
    for (int j = 0; j < N; j++) {
        float2 o  = shflx(x[j], mm);
        float2 ru = caddf(x[j], cmulf(o, wc));
        float2 rd = csubf(o, cmulf(x[j], wc));
        x[j] = up ? ru : rd;
    }
}
template <int N>
__device__ __forceinline__ void dit_shfl1(float2* x, int l) {   // mm=1, w=1
    bool up = (l & 1) == 0;
#pragma unroll
    for (int j = 0; j < N; j++) {
        float2 o  = shflx(x[j], 1);
        float2 ru = caddf(x[j], o);
        float2 rd = csubf(o, x[j]);
        x[j] = up ? ru : rd;
    }
}

// ============ 512-pt FFT, register twiddles (e = lane + 32*j, j<16) =========
__device__ __forceinline__ void fft512_dif_rt(float2 x[16], const Tw512& t, int l) {
#pragma unroll
    for (int j = 0; j < 8; j++) {                       // span 256: W_512^{l+32j}
        float2 w = cmulf(t.b512, C16f(j));
        float2 a = x[j], b = x[j + 8];
        x[j]     = caddf(a, b);
        x[j + 8] = cmulf(csubf(a, b), w);
    }
#pragma unroll
    for (int g = 0; g < 2; g++)                         // span 128: W_256^{l+32j0}
#pragma unroll
        for (int j0 = 0; j0 < 4; j0++) {
            int j = g * 8 + j0;
            float2 w = cmulf(t.b256, C8f(j0));
            float2 a = x[j], b = x[j + 4];
            x[j]     = caddf(a, b);
            x[j + 4] = cmulf(csubf(a, b), w);
        }
#pragma unroll
    for (int g = 0; g < 4; g++)                         // span 64: W_128^{l+32j0}
#pragma unroll
        for (int j0 = 0; j0 < 2; j0++) {
            int j = g * 4 + j0;
            float2 w = j0 ? cmul_mi(t.b128) : t.b128;
            float2 a = x[j], b = x[j + 2];
            x[j]     = caddf(a, b);
            x[j + 2] = cmulf(csubf(a, b), w);
        }
#pragma unroll
    for (int j = 0; j < 16; j += 2) {                   // span 32: W_64^l
        float2 a = x[j], b = x[j + 1];
        x[j]     = caddf(a, b);
        x[j + 1] = cmulf(csubf(a, b), t.b64);
    }
    dif_shfl<16>(x, 16, t.v16, l);
    dif_shfl<16>(x,  8, t.v8,  l);
    dif_shfl<16>(x,  4, t.v4,  l);
    dif_shfl<16>(x,  2, t.v2,  l);
    dif_shfl1<16>(x, l);
}

__device__ __forceinline__ void fft512_dit_rt(float2 x[16], const Tw512& t, int l) {
    dit_shfl1<16>(x, l);
    dit_shfl<16>(x,  2, conjf(t.v2),  l);
    dit_shfl<16>(x,  4, conjf(t.v4),  l);
    dit_shfl<16>(x,  8, conjf(t.v8),  l);
    dit_shfl<16>(x, 16, conjf(t.v16), l);
    {
        float2 w = conjf(t.b64);
#pragma unroll
        for (int j = 0; j < 16; j += 2) {
            float2 u = x[j], v = cmulf(x[j + 1], w);
            x[j]     = caddf(u, v);
            x[j + 1] = csubf(u, v);
        }
    }
#pragma unroll
    for (int g = 0; g < 4; g++)
#pragma unroll
        for (int j0 = 0; j0 < 2; j0++) {
            int j = g * 4 + j0;
            float2 w = conjf(j0 ? cmul_mi(t.b128) : t.b128);
            float2 u = x[j], v = cmulf(x[j + 2], w);
            x[j]     = caddf(u, v);
            x[j + 2] = csubf(u, v);
        }
#pragma unroll
    for (int g = 0; g < 2; g++)
#pragma unroll
        for (int j0 = 0; j0 < 4; j0++) {
            int j = g * 8 + j0;
            float2 w = conjf(cmulf(t.b256, C8f(j0)));
            float2 u = x[j], v = cmulf(x[j + 4], w);
            x[j]     = caddf(u, v);
            x[j + 4] = csubf(u, v);
        }
#pragma unroll
    for (int j = 0; j < 8; j++) {
        float2 w = conjf(cmulf(t.b512, C16f(j)));
        float2 u = x[j], v = cmulf(x[j + 8], w);
        x[j]     = caddf(u, v);
        x[j + 8] = csubf(u, v);
    }
}

// ============ 256-pt FFT, register twiddles (e = lane + 32*j, j<8) ==========
__device__ __forceinline__ void fft256_dif_rt(float2 x[8], const Tw512& t, int l) {
#pragma unroll
    for (int j = 0; j < 4; j++) {                       // span 128: W_256^{l+32j}
        float2 w = cmulf(t.b256, C8f(j));
        float2 a = x[j], b = x[j + 4];
        x[j]     = caddf(a, b);
        x[j + 4] = cmulf(csubf(a, b), w);
    }
#pragma unroll
    for (int g = 0; g < 2; g++)                         // span 64: W_128^{l+32j0}
#pragma unroll
        for (int j0 = 0; j0 < 2; j0++) {
            int j = g * 4 + j0;
            float2 w = j0 ? cmul_mi(t.b128) : t.b128;
            float2 a = x[j], b = x[j + 2];
            x[j]     = caddf(a, b);
            x[j + 2] = cmulf(csubf(a, b), w);
        }
#pragma unroll
    for (int j = 0; j < 8; j += 2) {                    // span 32: W_64^l
        float2 a = x[j], b = x[j + 1];
        x[j]     = caddf(a, b);
        x[j + 1] = cmulf(csubf(a, b), t.b64);
    }
    dif_shfl<8>(x, 16, t.v16, l);
    dif_shfl<8>(x,  8, t.v8,  l);
    dif_shfl<8>(x,  4, t.v4,  l);
    dif_shfl<8>(x,  2, t.v2,  l);
    dif_shfl1<8>(x, l);
}

__device__ __forceinline__ void fft256_dit_rt(float2 x[8], const Tw512& t, int l) {
    dit_shfl1<8>(x, l);
    dit_shfl<8>(x,  2, conjf(t.v2),  l);
    dit_shfl<8>(x,  4, conjf(t.v4),  l);
    dit_shfl<8>(x,  8, conjf(t.v8),  l);
    dit_shfl<8>(x, 16, conjf(t.v16), l);
    {
        float2 w = conjf(t.b64);
#pragma unroll
        for (int j = 0; j < 8; j += 2) {
            float2 u = x[j], v = cmulf(x[j + 1], w);
            x[j]     = caddf(u, v);
            x[j + 1] = csubf(u, v);
        }
    }
#pragma unroll
    for (int g = 0; g < 2; g++)
#pragma unroll
        for (int j0 = 0; j0 < 2; j0++) {
            int j = g * 4 + j0;
            float2 w = conjf(j0 ? cmul_mi(t.b128) : t.b128);
            float2 u = x[j], v = cmulf(x[j + 2], w);
            x[j]     = caddf(u, v);
            x[j + 2] = csubf(u, v);
        }
#pragma unroll
    for (int j = 0; j < 4; j++) {
        float2 w = conjf(cmulf(t.b256, C8f(j)));
        float2 u = x[j], v = cmulf(x[j + 4], w);
        x[j]     = caddf(u, v);
        x[j + 4] = csubf(u, v);
    }
}

// ---------------- K0 --------------------------------------------------------
__global__ void k_init() {
    int t = threadIdx.x;
    if (t < NIMG) { g_mn[t] = 0x7f800000u; g_mx[t] = 0u; }
    if (t == 0)   g_diff = 0.0;
}

// -------- K1: mf0 + R2C row FFT (256-pt packed) -> bufA[k][r], k=0..256 -----
__global__ void __launch_bounds__(256, 3) k_stage1(const float* __restrict__ inA,
                                                   const float* __restrict__ inB) {
    __shared__ float2 zs[8][289];
    int l  = threadIdx.x & 31, wp = threadIdx.x >> 5;
    int img = blockIdx.y;
    int r0  = blockIdx.x << 3;
    int row = r0 + wp;
    Tw512 t = make_tw(l);
    const float* src = (img < 64) ? (inA + (size_t)img * EL2)
                                  : (inB + (size_t)(img - 64) * EL2);
    const float2* rp = (const float2*)(src + (size_t)row * ELN);
    float2 x[8];
#pragma unroll
    for (int j = 0; j < 8; j++) {            // z[m] = mf0[2m] + i mf0[2m+1]
        float2 v = rp[l + 32 * j];
        x[j] = make_float2(__expf(-8.0f * v.x * v.x), __expf(-8.0f * v.y * v.y));
    }
    fft256_dif_rt(x, t, l);                   // pos p holds Z(rev8(p))
#pragma unroll
    for (int j = 0; j < 8; j++) { int p = l + 32 * j; zs[wp][sig(p)] = x[j]; }
    __syncwarp();
    // Hermitian unpack: H(k) = E + (-i W_512^k) O, E=(Z(k)+conj(Z(256-k)))/2
    float2 H[8];
#pragma unroll
    for (int j = 0; j < 8; j++) {
        int k  = l + 32 * j;                  // 0..255
        int k2 = (256 - k) & 255;
        float2 A  = zs[wp][sig(rev8(k))];     // Z(k)
        float2 Bc = zs[wp][sig(rev8(k2))];    // Z(256-k)
        float2 B  = make_float2(Bc.x, -Bc.y);
        float2 E  = make_float2(0.5f * (A.x + B.x), 0.5f * (A.y + B.y));
        float2 O  = make_float2(0.5f * (A.x - B.x), 0.5f * (A.y - B.y));
        float2 f  = cmul_mi(cmulf(t.b512, C16f(j)));   // -i * W_512^{l+32j}
        H[j] = caddf(E, cmulf(f, O));
    }
    float2 Z0 = zs[wp][0];                    // sig(0)=0; Z(0)
    __syncwarp();
#pragma unroll
    for (int j = 0; j < 8; j++) zs[wp][l + 32 * j] = H[j];
    if (l == 0) zs[wp][256] = make_float2(Z0.x - Z0.y, 0.0f);  // H(256)
    __syncthreads();
    float2* dst = g_bufA + (size_t)img * IMGSTRIDE;
    for (int i = threadIdx.x; i < 257 * 8; i += 256) {
        int k = i >> 3, rl = i & 7;
        dst[(size_t)k * ELN + r0 + rl] = zs[rl][k];
    }
}

// -------- K2: column FFT + power + column IFFT (per k1 = 0..256) ------------
// Post-power the column sequence is REAL -> inverse output is conjugate-even
// in y: c(y) = conj(c(512-y)). Store only y = 0..256.
__global__ void __launch_bounds__(256, 2) k_stage2() {
    __shared__ float2 sh[8][513];
    int l  = threadIdx.x & 31, wp = threadIdx.x >> 5;
    int img = blockIdx.y;
    int kb  = blockIdx.x << 3;                // 0..256 (33 blocks; pad rows stay 0)
    Tw512 t = make_tw(l);
    const float2* src = g_bufA + (size_t)img * IMGSTRIDE + (size_t)(kb + wp) * ELN;
    float2 x[16];
#pragma unroll
    for (int j = 0; j < 16; j++) x[j] = src[l + 32 * j];
    fft512_dif_rt(x, t, l);
#pragma unroll
    for (int j = 0; j < 16; j++) {            // power / (el*el), elementwise
        float p = (x[j].x * x[j].x + x[j].y * x[j].y) * (1.0f / 262144.0f);
        x[j] = make_float2(p, 0.0f);
    }
    fft512_dit_rt(x, t, l);
    const float sc = 1.0f / 512.0f;           // column half of ifft2 norm
#pragma unroll
    for (int j = 0; j < 16; j++)
        sh[wp][l + 32 * j] = make_float2(x[j].x * sc, x[j].y * sc);
    __syncthreads();
    float2* dst = g_bufB + (size_t)img * IMGSTRIDE;
    for (int i = threadIdx.x; i < 257 * 8; i += 256) {   // only y = 0..256
        int y = i >> 3, kl = i & 7;
        dst[(size_t)y * KROWS + kb + kl] = sh[kl][y];
    }
}

// -------- K3: C2R row inverse + fftshift + min/max + window write -----------
__global__ void __launch_bounds__(256, 3) k_stage3() {
    __shared__ float2 hs[8][289];
    __shared__ float  smn[8], smx[8];
    int l  = threadIdx.x & 31, wp = threadIdx.x >> 5;
    int img = blockIdx.y;
    int y   = (blockIdx.x << 3) + wp;
    Tw512 t = make_tw(l);
    // W_64^{rev5(l)} for the bit-reversed unpack twiddle
    int rl5 = __brev((unsigned)l) >> 27;      // rev5(l)
    float s5, c5;
    sincosf(-PI_F * (float)rl5 * (1.0f / 32.0f), &s5, &c5);
    float2 wl = make_float2(c5, s5);
    // conjugate-even reconstruction for y > 256
    int   ys  = (y <= 256) ? y : (512 - y);
    float cs  = (y <= 256) ? 1.0f : -1.0f;
    const float2* srcB = g_bufB + (size_t)img * IMGSTRIDE + (size_t)ys * KROWS;
#pragma unroll
    for (int j = 0; j < 8; j++) {
        int idx = l + 32 * j;
        float2 v = srcB[idx];
        hs[wp][sig(idx)] = make_float2(v.x, cs * v.y);
    }
    if (l == 0) {
        float2 v = srcB[256];
        hs[wp][sig(256)] = make_float2(v.x, cs * v.y);
    }
    __syncwarp();                             // hs[wp] is per-warp
    // Build Z(k) = E + iO at bit-rev positions for the 256-pt DIT
    float2 x[8];
#pragma unroll
    for (int j = 0; j < 8; j++) {
        int p  = l + 32 * j;
        int k  = rev8(p);                     // = 8*rev5(l) + rev3(j)
        int km = 256 - k;                     // 1..256
        float2 Hk = hs[wp][sig(k)];
        float2 Hm = hs[wp][sig(km)];          // conj applied below
        float2 E  = make_float2(0.5f * (Hk.x + Hm.x), 0.5f * (Hk.y - Hm.y));
        float2 Od = make_float2(0.5f * (Hk.x - Hm.x), 0.5f * (Hk.y + Hm.y));
        float2 wk = cmulf(wl, CRf(j));        // W_512^k = W_64^{rev5(l)} * W_512^{rev3(j)}
        float2 O  = cmulf(Od, conjf(wk));     // * W^{-k}
        x[j] = make_float2(E.x - O.y, E.y + O.x);   // E + i*O
    }
    fft256_dit_rt(x, t, l);                   // z(m) natural; x[2m]=z.x, x[2m+1]=z.y
    int yy = y ^ 256;                         // fftshift rows
    bool rowin = (yy >= WIN0) && (yy < WIN0 + WIN);
    float* wdst = g_win + (size_t)img * (WIN * WIN) + (size_t)(yy - WIN0) * WIN;
    float mn = 3.0e38f, mx = -3.0e38f;
#pragma unroll
    for (int j = 0; j < 8; j++) {
        float v0 = x[j].x * (1.0f / 256.0f);  // row half of ifft2 norm (C2R form)
        float v1 = x[j].y * (1.0f / 256.0f);
        mn = fminf(mn, fminf(v0, v1));
        mx = fmaxf(mx, fmaxf(v0, v1));
        int m  = l + 32 * j;
        int ms = m ^ 128;                     // shifted col pair (2ms, 2ms+1)
        if (rowin && ms >= 64 && ms < 192)    // cols in [128, 384)
            ((float2*)wdst)[ms - 64] = make_float2(v0, v1);
    }
#pragma unroll
    for (int o = 16; o; o >>= 1) {
        mn = fminf(mn, __shfl_xor_sync(0xffffffffu, mn, o));
        mx = fmaxf(mx, __shfl_xor_sync(0xffffffffu, mx, o));
    }
    if (l == 0) { smn[wp] = mn; smx[wp] = mx; }
    __syncthreads();
    if (threadIdx.x == 0) {
        float m1 = smn[0], m2 = smx[0];
#pragma unroll
        for (int i = 1; i < 8; i++) { m1 = fminf(m1, smn[i]); m2 = fmaxf(m2, smx[i]); }
        atomicMin(&g_mn[img], __float_as_uint(m1));   // ac > 0 -> uint order ok
        atomicMax(&g_mx[img], __float_as_uint(m2));
    }
}

// -------- K4: raw copy + normalize*mask window + zeros + MSE ----------------
__global__ void __launch_bounds__(256) k_final(const float* __restrict__ inA,
                                               const float* __restrict__ inB,
                                               float* __restrict__ out) {
    __shared__ float ssum[8];
    int b = blockIdx.y;            // image 0..63
    int r = blockIdx.x;            // row 0..511
    float mnI = __uint_as_float(g_mn[b]);
    float mxI = __uint_as_float(g_mx[b]);
    float mnT = __uint_as_float(g_mn[b + 64]);
    float mxT = __uint_as_float(g_mx[b + 64]);
    float sI = 1.0f / (mxI - mnI + 1e-12f);
    float sT = 1.0f / (mxT - mnT + 1e-12f);
    const float* rawI = inA + (size_t)b * EL2 + (size_t)r * ELN;
    const float* rawT = inB + (size_t)b * EL2 + (size_t)r * ELN;
    const float* winI = g_win + (size_t)b * (WIN * WIN) + (size_t)(r - WIN0) * WIN;
    const float* winT = g_win + (size_t)(b + 64) * (WIN * WIN) + (size_t)(r - WIN0) * WIN;
    float* oI = out + 1 + (size_t)b * (ELN * 1024) + (size_t)r * 1024;
    float* oT = oI + (size_t)64 * ELN * 1024;
    bool rowin = (r >= WIN0) && (r < WIN0 + WIN);
    float dy = (float)(r - 256);
    float dy2 = dy * dy;
    float ls = 0.0f;
#pragma unroll
    for (int it = 0; it < 2; it++) {
        int c = threadIdx.x + it * 256;
        oI[c] = rawI[c];
        oT[c] = rawT[c];
        float ia = 0.0f, ta = 0.0f;
        if (rowin && c >= WIN0 && c < WIN0 + WIN) {
            float vI = winI[c - WIN0];
            float vT = winT[c - WIN0];
            float dx = (float)(c - 256);
            float mask = __expf(-fmaf(dx, dx, dy2) * (1.0f / 800.0f));
            ia = (vI - mnI) * sI * mask;
            ta = (vT - mnT) * sT * mask;
            float d = ia - ta;
            ls = fmaf(d, d, ls);
        }
        oI[512 + c] = ia;
        oT[512 + c] = ta;
    }
    int l = threadIdx.x & 31, wp = threadIdx.x >> 5;
#pragma unroll
    for (int o = 16; o; o >>= 1) ls += __shfl_xor_sync(0xffffffffu, ls, o);
    if (l == 0) ssum[wp] = ls;
    __syncthreads();
    if (threadIdx.x == 0) {
        float t = ssum[0];
#pragma unroll
        for (int i = 1; i < 8; i++) t += ssum[i];
        atomicAdd(&g_diff, (double)t);
    }
}

__global__ void k_write(float* __restrict__ out) {
    out[0] = (float)(g_diff * (1.0 / 16777216.0));   // mean over B*el*el
}

// ---------------- launch ----------------------------------------------------
extern "C" void kernel_launch(void* const* d_in, const int* in_sizes, int n_in,
                              void* d_out, int out_size) {
    const float* inA = (const float*)d_in[0];
    const float* inB = (const float*)d_in[1];
    float* out = (float*)d_out;
    (void)in_sizes; (void)n_in; (void)out_size;

    k_init  <<<1, 128>>>();
    k_stage1<<<dim3(64, 128), 256>>>(inA, inB);
    k_stage2<<<dim3(33, 128), 256>>>();
    k_stage3<<<dim3(64, 128), 256>>>();
    k_final <<<dim3(512, 64), 256>>>(inA, inB, out);
    k_write <<<1, 1>>>(out);
}

// round 13
// speedup vs baseline: 1.3427x; 1.0802x over previous
#include <cuda_runtime.h>
#include <cstdint>

#define ELN   512
#define EL2   (512*512)
#define NIMG  128
#define KROWS 264                         // 257 used, padded to 264 (mult of 8)
#define IMGSTRIDE ((size_t)KROWS * ELN)   // complex elements per image
#define WIN   256
#define WIN0  128
#define PI_F  3.14159265358979323846f

// ---------------- device scratch (allocation-free) -------------------------
__device__ float2   g_bufA[(size_t)NIMG * KROWS * ELN];   // ~138 MB
__device__ float2   g_bufB[(size_t)NIMG * KROWS * ELN];   // ~138 MB (y=0..256 used)
__device__ float    g_win [(size_t)NIMG * WIN * WIN];     // 33.5 MB center window
__device__ unsigned g_mn[NIMG], g_mx[NIMG];
__device__ double   g_diff;

// ---------------- complex helpers -----------------------------------------
__device__ __forceinline__ float2 cmulf(float2 a, float2 b) {
    return make_float2(a.x * b.x - a.y * b.y, a.x * b.y + a.y * b.x);
}
__device__ __forceinline__ float2 caddf(float2 a, float2 b) {
    return make_float2(a.x + b.x, a.y + b.y);
}
__device__ __forceinline__ float2 csubf(float2 a, float2 b) {
    return make_float2(a.x - b.x, a.y - b.y);
}
__device__ __forceinline__ float2 csq(float2 a) {
    return make_float2(a.x * a.x - a.y * a.y, 2.0f * a.x * a.y);
}
__device__ __forceinline__ float2 cneg(float2 a)  { return make_float2(-a.x, -a.y); }
__device__ __forceinline__ float2 conjf(float2 a) { return make_float2(a.x, -a.y); }
__device__ __forceinline__ float2 cmul_mi(float2 a) { return make_float2(a.y, -a.x); } // a * (-i)
__device__ __forceinline__ float2 shflx(float2 v, int m) {
    v.x = __shfl_xor_sync(0xffffffffu, v.x, m);
    v.y = __shfl_xor_sync(0xffffffffu, v.y, m);
    return v;
}
__device__ __forceinline__ int rev8(int k) { return __brev((unsigned)k) >> 24; }
__device__ __forceinline__ int sig(int k)  { return k ^ (k >> 4); }  // bank swizzle

// Compile-time twiddle constants
__device__ __forceinline__ float2 C16f(int j) {   // W_16^j = exp(-i pi j/8)
    const float2 C[8] = {
        { 1.0f, 0.0f}, { 0.92387953f,-0.38268343f}, { 0.70710678f,-0.70710678f},
        { 0.38268343f,-0.92387953f}, { 0.0f,-1.0f}, {-0.38268343f,-0.92387953f},
        {-0.70710678f,-0.70710678f}, {-0.92387953f,-0.38268343f}};
    return C[j];
}
__device__ __forceinline__ float2 C8f(int j) {    // W_8^j = exp(-i pi j/4)
    const float2 C[4] = {
        {1.0f, 0.0f}, {0.70710678f,-0.70710678f}, {0.0f,-1.0f},
        {-0.70710678f,-0.70710678f}};
    return C[j];
}
__device__ __forceinline__ float2 CRf(int j) {    // W_512^{rev3(j)}
    const float2 C[8] = {
        {1.0f, 0.0f},               {0.99879546f,-0.04906767f},
        {0.99969882f,-0.02454123f}, {0.99729046f,-0.07356456f},
        {0.99992470f,-0.01227154f}, {0.99811811f,-0.06132074f},
        {0.99932238f,-0.03680722f}, {0.99631261f,-0.08579731f}};
    return C[j];
}

// ---------------- register twiddles (no shared table) ----------------------
struct Tw512 { float2 b512, b256, b128, b64, v16, v8, v4, v2; };

__device__ __forceinline__ Tw512 make_tw(int l) {
    Tw512 t; float s, c;
    sincosf(-PI_F * (float)l * (1.0f / 256.0f), &s, &c);
    t.b512 = make_float2(c, s);          // W_512^l
    t.b256 = csq(t.b512);                // W_256^l
    t.b128 = csq(t.b256);                // W_128^l
    t.b64  = csq(t.b128);                // W_64^l
    float2 v = csq(t.b64); if (l & 16) v = cneg(v); t.v16 = v;   // W_32^{l&15}
    v = csq(v);            if (l & 8)  v = cneg(v); t.v8  = v;   // W_16^{l&7}
    v = csq(v);            if (l & 4)  v = cneg(v); t.v4  = v;   // W_8^{l&3}
    v = csq(v);            if (l & 2)  v = cneg(v); t.v2  = v;   // W_4^{l&1}
    return t;
}

// ---------------- shuffle-stage helpers (single-formula, no select) --------
// DIF stage: o = shfl(x); a = o + s*x; x = a * w_l  (w_l = up ? 1 : w)
template <int N>
__device__ __forceinline__ void dif_shfl(float2* x, int mm, float2 w, int l) {
    bool up = (l & mm) == 0;
    float s = up ? 1.0f : -1.0f;
    float2 wl = up ? make_float2(1.0f, 0.0f) : w;
#pragma unroll
    for (int j = 0; j < N; j++) {
        float2 o = shflx(x[j], mm);
        float2 a = make_float2(fmaf(s, x[j].x, o.x), fmaf(s, x[j].y, o.y));
        x[j] = cmulf(a, wl);
    }
}
template <int N>
__device__ __forceinline__ void dif_shfl1(float2* x, int l) {   // mm=1, w=1
    float s = (l & 1) ? -1.0f : 1.0f;
#pragma unroll
    for (int j = 0; j < N; j++) {
        float2 o = shflx(x[j], 1);
        x[j] = make_float2(fmaf(s, x[j].x, o.x), fmaf(s, x[j].y, o.y));
    }
}
// DIT stage: y = x * v_l (v_l = up ? 1 : wc); o = shfl(y); x = o + s*y
template <int N>
__device__ __forceinline__ void dit_shfl(float2* x, int mm, float2 wc, int l) {
    bool up = (l & mm) == 0;
    float s = up ? 1.0f : -1.0f;
    float2 vl = up ? make_float2(1.0f, 0.0f) : wc;
#pragma unroll
    for (int j = 0; j < N; j++) {
        float2 y = cmulf(x[j], vl);
        float2 o = shflx(y, mm);
        x[j] = make_float2(fmaf(s, y.x, o.x), fmaf(s, y.y, o.y));
    }
}
template <int N>
__device__ __forceinline__ void dit_shfl1(float2* x, int l) {   // mm=1, w=1
    float s = (l & 1) ? -1.0f : 1.0f;
#pragma unroll
    for (int j = 0; j < N; j++) {
        float2 o = shflx(x[j], 1);
        x[j] = make_float2(fmaf(s, x[j].x, o.x), fmaf(s, x[j].y, o.y));
    }
}

// ============ 512-pt FFT, register twiddles (e = lane + 32*j, j<16) =========
__device__ __forceinline__ void fft512_dif_rt(float2 x[16], const Tw512& t, int l) {
#pragma unroll
    for (int j = 0; j < 8; j++) {                       // span 256: W_512^{l+32j}
        float2 w = cmulf(t.b512, C16f(j));
        float2 a = x[j], b = x[j + 8];
        x[j]     = caddf(a, b);
        x[j + 8] = cmulf(csubf(a, b), w);
    }
#pragma unroll
    for (int g = 0; g < 2; g++)                         // span 128: W_256^{l+32j0}
#pragma unroll
        for (int j0 = 0; j0 < 4; j0++) {
            int j = g * 8 + j0;
            float2 w = cmulf(t.b256, C8f(j0));
            float2 a = x[j], b = x[j + 4];
            x[j]     = caddf(a, b);
            x[j + 4] = cmulf(csubf(a, b), w);
        }
#pragma unroll
    for (int g = 0; g < 4; g++)                         // span 64: W_128^{l+32j0}
#pragma unroll
        for (int j0 = 0; j0 < 2; j0++) {
            int j = g * 4 + j0;
            float2 w = j0 ? cmul_mi(t.b128) : t.b128;
            float2 a = x[j], b = x[j + 2];
            x[j]     = caddf(a, b);
            x[j + 2] = cmulf(csubf(a, b), w);
        }
#pragma unroll
    for (int j = 0; j < 16; j += 2) {                   // span 32: W_64^l
        float2 a = x[j], b = x[j + 1];
        x[j]     = caddf(a, b);
        x[j + 1] = cmulf(csubf(a, b), t.b64);
    }
    dif_shfl<16>(x, 16, t.v16, l);
    dif_shfl<16>(x,  8, t.v8,  l);
    dif_shfl<16>(x,  4, t.v4,  l);
    dif_shfl<16>(x,  2, t.v2,  l);
    dif_shfl1<16>(x, l);
}

__device__ __forceinline__ void fft512_dit_rt(float2 x[16], const Tw512& t, int l) {
    dit_shfl1<16>(x, l);
    dit_shfl<16>(x,  2, conjf(t.v2),  l);
    dit_shfl<16>(x,  4, conjf(t.v4),  l);
    dit_shfl<16>(x,  8, conjf(t.v8),  l);
    dit_shfl<16>(x, 16, conjf(t.v16), l);
    {
        float2 w = conjf(t.b64);
#pragma unroll
        for (int j = 0; j < 16; j += 2) {
            float2 u = x[j], v = cmulf(x[j + 1], w);
            x[j]     = caddf(u, v);
            x[j + 1] = csubf(u, v);
        }
    }
#pragma unroll
    for (int g = 0; g < 4; g++)
#pragma unroll
        for (int j0 = 0; j0 < 2; j0++) {
            int j = g * 4 + j0;
            float2 w = conjf(j0 ? cmul_mi(t.b128) : t.b128);
            float2 u = x[j], v = cmulf(x[j + 2], w);
            x[j]     = caddf(u, v);
            x[j + 2] = csubf(u, v);
        }
#pragma unroll
    for (int g = 0; g < 2; g++)
#pragma unroll
        for (int j0 = 0; j0 < 4; j0++) {
            int j = g * 8 + j0;
            float2 w = conjf(cmulf(t.b256, C8f(j0)));
            float2 u = x[j], v = cmulf(x[j + 4], w);
            x[j]     = caddf(u, v);
            x[j + 4] = csubf(u, v);
        }
#pragma unroll
    for (int j = 0; j < 8; j++) {
        float2 w = conjf(cmulf(t.b512, C16f(j)));
        float2 u = x[j], v = cmulf(x[j + 8], w);
        x[j]     = caddf(u, v);
        x[j + 8] = csubf(u, v);
    }
}

// ============ 256-pt FFT, register twiddles (e = lane + 32*j, j<8) ==========
__device__ __forceinline__ void fft256_dif_rt(float2 x[8], const Tw512& t, int l) {
#pragma unroll
    for (int j = 0; j < 4; j++) {                       // span 128: W_256^{l+32j}
        float2 w = cmulf(t.b256, C8f(j));
        float2 a = x[j], b = x[j + 4];
        x[j]     = caddf(a, b);
        x[j + 4] = cmulf(csubf(a, b), w);
    }
#pragma unroll
    for (int g = 0; g < 2; g++)                         // span 64: W_128^{l+32j0}
#pragma unroll
        for (int j0 = 0; j0 < 2; j0++) {
            int j = g * 4 + j0;
            float2 w = j0 ? cmul_mi(t.b128) : t.b128;
            float2 a = x[j], b = x[j + 2];
            x[j]     = caddf(a, b);
            x[j + 2] = cmulf(csubf(a, b), w);
        }
#pragma unroll
    for (int j = 0; j < 8; j += 2) {                    // span 32: W_64^l
        float2 a = x[j], b = x[j + 1];
        x[j]     = caddf(a, b);
        x[j + 1] = cmulf(csubf(a, b), t.b64);
    }
    dif_shfl<8>(x, 16, t.v16, l);
    dif_shfl<8>(x,  8, t.v8,  l);
    dif_shfl<8>(x,  4, t.v4,  l);
    dif_shfl<8>(x,  2, t.v2,  l);
    dif_shfl1<8>(x, l);
}

__device__ __forceinline__ void fft256_dit_rt(float2 x[8], const Tw512& t, int l) {
    dit_shfl1<8>(x, l);
    dit_shfl<8>(x,  2, conjf(t.v2),  l);
    dit_shfl<8>(x,  4, conjf(t.v4),  l);
    dit_shfl<8>(x,  8, conjf(t.v8),  l);
    dit_shfl<8>(x, 16, conjf(t.v16), l);
    {
        float2 w = conjf(t.b64);
#pragma unroll
        for (int j = 0; j < 8; j += 2) {
            float2 u = x[j], v = cmulf(x[j + 1], w);
            x[j]     = caddf(u, v);
            x[j + 1] = csubf(u, v);
        }
    }
#pragma unroll
    for (int g = 0; g < 2; g++)
#pragma unroll
        for (int j0 = 0; j0 < 2; j0++) {
            int j = g * 4 + j0;
            float2 w = conjf(j0 ? cmul_mi(t.b128) : t.b128);
            float2 u = x[j], v = cmulf(x[j + 2], w);
            x[j]     = caddf(u, v);
            x[j + 2] = csubf(u, v);
        }
#pragma unroll
    for (int j = 0; j < 4; j++) {
        float2 w = conjf(cmulf(t.b256, C8f(j)));
        float2 u = x[j], v = cmulf(x[j + 4], w);
        x[j]     = caddf(u, v);
        x[j + 4] = csubf(u, v);
    }
}

// ---------------- K0 --------------------------------------------------------
__global__ void k_init() {
    int t = threadIdx.x;
    if (t < NIMG) { g_mn[t] = 0x7f800000u; g_mx[t] = 0u; }
    if (t == 0)   g_diff = 0.0;
}

// -------- K1: mf0 + R2C row FFT (256-pt packed) -> bufA[k][r], k=0..256 -----
__global__ void __launch_bounds__(256, 3) k_stage1(const float* __restrict__ inA,
                                                   const float* __restrict__ inB) {
    __shared__ float2 zs[8][289];
    int l  = threadIdx.x & 31, wp = threadIdx.x >> 5;
    int img = blockIdx.y;
    int r0  = blockIdx.x << 3;
    int row = r0 + wp;
    Tw512 t = make_tw(l);
    const float* src = (img < 64) ? (inA + (size_t)img * EL2)
                                  : (inB + (size_t)(img - 64) * EL2);
    const float2* rp = (const float2*)(src + (size_t)row * ELN);
    float2 x[8];
#pragma unroll
    for (int j = 0; j < 8; j++) {            // z[m] = mf0[2m] + i mf0[2m+1]
        float2 v = rp[l + 32 * j];
        x[j] = make_float2(__expf(-8.0f * v.x * v.x), __expf(-8.0f * v.y * v.y));
    }
    fft256_dif_rt(x, t, l);                   // pos p holds Z(rev8(p))
#pragma unroll
    for (int j = 0; j < 8; j++) { int p = l + 32 * j; zs[wp][sig(p)] = x[j]; }
    __syncwarp();
    // Hermitian unpack: H(k) = E + (-i W_512^k) O, E=(Z(k)+conj(Z(256-k)))/2
    float2 H[8];
#pragma unroll
    for (int j = 0; j < 8; j++) {
        int k  = l + 32 * j;                  // 0..255
        int k2 = (256 - k) & 255;
        float2 A  = zs[wp][sig(rev8(k))];     // Z(k)
        float2 Bc = zs[wp][sig(rev8(k2))];    // Z(256-k)
        float2 B  = make_float2(Bc.x, -Bc.y);
        float2 E  = make_float2(0.5f * (A.x + B.x), 0.5f * (A.y + B.y));
        float2 O  = make_float2(0.5f * (A.x - B.x), 0.5f * (A.y - B.y));
        float2 f  = cmul_mi(cmulf(t.b512, C16f(j)));   // -i * W_512^{l+32j}
        H[j] = caddf(E, cmulf(f, O));
    }
    float2 Z0 = zs[wp][0];                    // sig(0)=0; Z(0)
    __syncwarp();
#pragma unroll
    for (int j = 0; j < 8; j++) zs[wp][l + 32 * j] = H[j];
    if (l == 0) zs[wp][256] = make_float2(Z0.x - Z0.y, 0.0f);  // H(256)
    __syncthreads();
    float2* dst = g_bufA + (size_t)img * IMGSTRIDE;
    for (int i = threadIdx.x; i < 257 * 8; i += 256) {
        int k = i >> 3, rl = i & 7;
        dst[(size_t)k * ELN + r0 + rl] = zs[rl][k];
    }
}

// -------- K2: column FFT + power + column IFFT (per k1 = 0..256) ------------
// Post-power the column sequence is REAL -> inverse output is conjugate-even
// in y: c(y) = conj(c(512-y)). Store only y = 0..256.
__global__ void __launch_bounds__(256, 2) k_stage2() {
    __shared__ float2 sh[8][513];
    int l  = threadIdx.x & 31, wp = threadIdx.x >> 5;
    int img = blockIdx.y;
    int kb  = blockIdx.x << 3;                // 0..256 (33 blocks; pad rows stay 0)
    Tw512 t = make_tw(l);
    const float2* src = g_bufA + (size_t)img * IMGSTRIDE + (size_t)(kb + wp) * ELN;
    float2 x[16];
#pragma unroll
    for (int j = 0; j < 16; j++) x[j] = src[l + 32 * j];
    fft512_dif_rt(x, t, l);
#pragma unroll
    for (int j = 0; j < 16; j++) {            // power / (el*el), elementwise
        float p = (x[j].x * x[j].x + x[j].y * x[j].y) * (1.0f / 262144.0f);
        x[j] = make_float2(p, 0.0f);
    }
    fft512_dit_rt(x, t, l);
    const float sc = 1.0f / 512.0f;           // column half of ifft2 norm
#pragma unroll
    for (int j = 0; j < 16; j++)
        sh[wp][l + 32 * j] = make_float2(x[j].x * sc, x[j].y * sc);
    __syncthreads();
    float2* dst = g_bufB + (size_t)img * IMGSTRIDE;
    for (int i = threadIdx.x; i < 257 * 8; i += 256) {   // only y = 0..256
        int y = i >> 3, kl = i & 7;
        dst[(size_t)y * KROWS + kb + kl] = sh[kl][y];
    }
}

// -------- K3: C2R row inverse + fftshift + min/max + window write -----------
__global__ void __launch_bounds__(256, 3) k_stage3() {
    __shared__ float2 hs[8][289];
    __shared__ float  smn[8], smx[8];
    int l  = threadIdx.x & 31, wp = threadIdx.x >> 5;
    int img = blockIdx.y;
    int y   = (blockIdx.x << 3) + wp;
    Tw512 t = make_tw(l);
    // W_64^{rev5(l)} for the bit-reversed unpack twiddle
    int rl5 = __brev((unsigned)l) >> 27;      // rev5(l)
    float s5, c5;
    sincosf(-PI_F * (float)rl5 * (1.0f / 32.0f), &s5, &c5);
    float2 wl = make_float2(c5, s5);
    // conjugate-even reconstruction for y > 256
    int   ys  = (y <= 256) ? y : (512 - y);
    float cs  = (y <= 256) ? 1.0f : -1.0f;
    const float2* srcB = g_bufB + (size_t)img * IMGSTRIDE + (size_t)ys * KROWS;
#pragma unroll
    for (int j = 0; j < 8; j++) {
        int idx = l + 32 * j;
        float2 v = srcB[idx];
        hs[wp][sig(idx)] = make_float2(v.x, cs * v.y);
    }
    if (l == 0) {
        float2 v = srcB[256];
        hs[wp][sig(256)] = make_float2(v.x, cs * v.y);
    }
    __syncwarp();                             // hs[wp] is per-warp
    // Build Z(k) = E + iO at bit-rev positions for the 256-pt DIT
    float2 x[8];
#pragma unroll
    for (int j = 0; j < 8; j++) {
        int p  = l + 32 * j;
        int k  = rev8(p);                     // = 8*rev5(l) + rev3(j)
        int km = 256 - k;                     // 1..256
        float2 Hk = hs[wp][sig(k)];
        float2 Hm = hs[wp][sig(km)];          // conj applied below
        float2 E  = make_float2(0.5f * (Hk.x + Hm.x), 0.5f * (Hk.y - Hm.y));
        float2 Od = make_float2(0.5f * (Hk.x - Hm.x), 0.5f * (Hk.y + Hm.y));
        float2 wk = cmulf(wl, CRf(j));        // W_512^k = W_64^{rev5(l)} * W_512^{rev3(j)}
        float2 O  = cmulf(Od, conjf(wk));     // * W^{-k}
        x[j] = make_float2(E.x - O.y, E.y + O.x);   // E + i*O
    }
    fft256_dit_rt(x, t, l);                   // z(m) natural; x[2m]=z.x, x[2m+1]=z.y
    int yy = y ^ 256;                         // fftshift rows
    bool rowin = (yy >= WIN0) && (yy < WIN0 + WIN);
    float* wdst = g_win + (size_t)img * (WIN * WIN) + (size_t)(yy - WIN0) * WIN;
    float mn = 3.0e38f, mx = -3.0e38f;
#pragma unroll
    for (int j = 0; j < 8; j++) {
        float v0 = x[j].x * (1.0f / 256.0f);  // row half of ifft2 norm (C2R form)
        float v1 = x[j].y * (1.0f / 256.0f);
        mn = fminf(mn, fminf(v0, v1));
        mx = fmaxf(mx, fmaxf(v0, v1));
        int m  = l + 32 * j;
        int ms = m ^ 128;                     // shifted col pair (2ms, 2ms+1)
        if (rowin && ms >= 64 && ms < 192)    // cols in [128, 384)
            ((float2*)wdst)[ms - 64] = make_float2(v0, v1);
    }
#pragma unroll
    for (int o = 16; o; o >>= 1) {
        mn = fminf(mn, __shfl_xor_sync(0xffffffffu, mn, o));
        mx = fmaxf(mx, __shfl_xor_sync(0xffffffffu, mx, o));
    }
    if (l == 0) { smn[wp] = mn; smx[wp] = mx; }
    __syncthreads();
    if (threadIdx.x == 0) {
        float m1 = smn[0], m2 = smx[0];
#pragma unroll
        for (int i = 1; i < 8; i++) { m1 = fminf(m1, smn[i]); m2 = fmaxf(m2, smx[i]); }
        atomicMin(&g_mn[img], __float_as_uint(m1));   // ac > 0 -> uint order ok
        atomicMax(&g_mx[img], __float_as_uint(m2));
    }
}

// -------- K4: raw copy + normalize*mask window + zeros + MSE ----------------
__global__ void __launch_bounds__(256) k_final(const float* __restrict__ inA,
                                               const float* __restrict__ inB,
                                               float* __restrict__ out) {
    __shared__ float ssum[8];
    int b = blockIdx.y;            // image 0..63
    int r = blockIdx.x;            // row 0..511
    float mnI = __uint_as_float(g_mn[b]);
    float mxI = __uint_as_float(g_mx[b]);
    float mnT = __uint_as_float(g_mn[b + 64]);
    float mxT = __uint_as_float(g_mx[b + 64]);
    float sI = 1.0f / (mxI - mnI + 1e-12f);
    float sT = 1.0f / (mxT - mnT + 1e-12f);
    const float* rawI = inA + (size_t)b * EL2 + (size_t)r * ELN;
    const float* rawT = inB + (size_t)b * EL2 + (size_t)r * ELN;
    const float* winI = g_win + (size_t)b * (WIN * WIN) + (size_t)(r - WIN0) * WIN;
    const float* winT = g_win + (size_t)(b + 64) * (WIN * WIN) + (size_t)(r - WIN0) * WIN;
    float* oI = out + 1 + (size_t)b * (ELN * 1024) + (size_t)r * 1024;
    float* oT = oI + (size_t)64 * ELN * 1024;
    bool rowin = (r >= WIN0) && (r < WIN0 + WIN);
    float dy = (float)(r - 256);
    float dy2 = dy * dy;
    float ls = 0.0f;
#pragma unroll
    for (int it = 0; it < 2; it++) {
        int c = threadIdx.x + it * 256;
        oI[c] = rawI[c];
        oT[c] = rawT[c];
        float ia = 0.0f, ta = 0.0f;
        if (rowin && c >= WIN0 && c < WIN0 + WIN) {
            float vI = winI[c - WIN0];
            float vT = winT[c - WIN0];
            float dx = (float)(c - 256);
            float mask = __expf(-fmaf(dx, dx, dy2) * (1.0f / 800.0f));
            ia = (vI - mnI) * sI * mask;
            ta = (vT - mnT) * sT * mask;
            float d = ia - ta;
            ls = fmaf(d, d, ls);
        }
        oI[512 + c] = ia;
        oT[512 + c] = ta;
    }
    int l = threadIdx.x & 31, wp = threadIdx.x >> 5;
#pragma unroll
    for (int o = 16; o; o >>= 1) ls += __shfl_xor_sync(0xffffffffu, ls, o);
    if (l == 0) ssum[wp] = ls;
    __syncthreads();
    if (threadIdx.x == 0) {
        float t = ssum[0];
#pragma unroll
        for (int i = 1; i < 8; i++) t += ssum[i];
        atomicAdd(&g_diff, (double)t);
    }
}

__global__ void k_write(float* __restrict__ out) {
    out[0] = (float)(g_diff * (1.0 / 16777216.0));   // mean over B*el*el
}

// ---------------- launch ----------------------------------------------------
extern "C" void kernel_launch(void* const* d_in, const int* in_sizes, int n_in,
                              void* d_out, int out_size) {
    const float* inA = (const float*)d_in[0];
    const float* inB = (const float*)d_in[1];
    float* out = (float*)d_out;
    (void)in_sizes; (void)n_in; (void)out_size;

    k_init  <<<1, 128>>>();
    k_stage1<<<dim3(64, 128), 256>>>(inA, inB);
    k_stage2<<<dim3(33, 128), 256>>>();
    k_stage3<<<dim3(64, 128), 256>>>();
    k_final <<<dim3(512, 64), 256>>>(inA, inB, out);
    k_write <<<1, 1>>>(out);
}